// round 4
// baseline (speedup 1.0000x reference)
#include <cuda_runtime.h>
#include <math.h>
#include <stdint.h>

// Problem constants (B=64, H=W=56, C=128)
#define BB 64
#define HH 56
#define WW 56
#define CC 128
#define LL (HH*WW)            // 3136
#define MM (BB*LL)            // 200704
#define HID 512
#define FWLD 260              // 2C + FOCAL_LEVEL + 1

// ---------------- scratch (device globals; no allocs allowed) ----------------
__device__ float g_y[(size_t)MM*CC];
__device__ float g_q[(size_t)MM*CC];
__device__ float g_ctx0[(size_t)MM*CC];
__device__ float g_ctx1[(size_t)MM*CC];
__device__ float g_ctxall[(size_t)MM*CC];
__device__ float g_gates[(size_t)MM*4];
__device__ float g_pool[BB*CC];
__device__ float g_x1[(size_t)MM*CC];
__device__ float g_hidden[(size_t)MM*HID];
__device__ float g_wt[196608];             // packed tf32-rounded weights [K,N]

#define WT_FWQ  0        // [128,128]
#define WT_FWC  16384    // [128,128]
#define WT_H    32768    // [128,128]
#define WT_PROJ 49152    // [128,128]
#define WT_FC1  65536    // [128,512]
#define WT_FC2  131072   // [512,128]

__device__ __forceinline__ float gelu_f(float x) {
    return 0.5f * x * (1.0f + erff(x * 0.7071067811865475f));
}
__device__ __forceinline__ float tf32r(float x) {
    uint32_t u; asm("cvt.rna.tf32.f32 %0, %1;" : "=r"(u) : "f"(x));
    return __uint_as_float(u);
}
__device__ __forceinline__ uint32_t smem_u32(const void* p) {
    uint32_t a;
    asm("{ .reg .u64 t; cvta.to.shared.u64 t, %1; cvt.u32.u64 %0, t; }" : "=r"(a) : "l"(p));
    return a;
}
__device__ __forceinline__ void cp16(uint32_t dst, const void* src) {
    asm volatile("cp.async.cg.shared.global [%0], [%1], 16;" :: "r"(dst), "l"(src));
}
__device__ __forceinline__ void mma_tf32(float* d, const uint32_t* a, const uint32_t* b) {
    asm volatile(
        "mma.sync.aligned.m16n8k8.row.col.f32.tf32.tf32.f32 "
        "{%0,%1,%2,%3}, {%4,%5,%6,%7}, {%8,%9}, {%0,%1,%2,%3};"
        : "+f"(d[0]), "+f"(d[1]), "+f"(d[2]), "+f"(d[3])
        : "r"(a[0]), "r"(a[1]), "r"(a[2]), "r"(a[3]), "r"(b[0]), "r"(b[1]));
}

// ======== tf32 mma.sync GEMM: C[M,N] = epi(A[M,K] @ B[K,N] + bias) ========
// grid (M/128, N/128), 256 threads (8 warps, 2x4), warp tile 64x32, BK=16.
// EPI: 0 none, 1 gelu(+tf32 round), 2 *extra(+round), 3 +extra.
template<int EPI>
__global__ void __launch_bounds__(256, 2)
mma_gemm(const float* __restrict__ A, int lda,
         const float* __restrict__ B, int ldb,
         const float* __restrict__ bias,
         float* __restrict__ C, int ldc,
         const float* __restrict__ extra, int lde,
         int K)
{
    __shared__ float As[2][128][20];   // [buf][m][k] pad->20 (80B rows, 16B aligned)
    __shared__ float Bs[2][16][136];   // [buf][k][n] pad->136

    const int tid  = threadIdx.x;
    const int lane = tid & 31, warp = tid >> 5;
    const int row  = lane >> 2, col = lane & 3;
    const int wm   = (warp >> 2) * 64;      // 0 / 64
    const int wn   = (warp & 3) * 32;       // 0 / 32 / 64 / 96
    const int m0   = blockIdx.x * 128, n0 = blockIdx.y * 128;

    const uint32_t sA = smem_u32(As), sB = smem_u32(Bs);
    const float* Ab = A + (size_t)m0 * lda;

    float acc[4][4][4];
    #pragma unroll
    for (int i = 0; i < 4; i++)
        #pragma unroll
        for (int j = 0; j < 4; j++)
            #pragma unroll
            for (int r = 0; r < 4; r++) acc[i][j][r] = 0.0f;

    auto load_chunk = [&](int kc, int buf) {
        #pragma unroll
        for (int i = 0; i < 2; i++) {          // A: 128 rows x 16 floats
            int idx = tid + i * 256;
            int r = idx >> 2, f4 = idx & 3;
            cp16(sA + (uint32_t)(((buf * 128 + r) * 20 + f4 * 4) * 4),
                 Ab + (size_t)r * lda + kc + f4 * 4);
        }
        #pragma unroll
        for (int i = 0; i < 2; i++) {          // B: 16 rows x 128 floats
            int idx = tid + i * 256;
            int r = idx >> 5, c4 = idx & 31;
            cp16(sB + (uint32_t)(((buf * 16 + r) * 136 + c4 * 4) * 4),
                 B + (size_t)(kc + r) * ldb + n0 + c4 * 4);
        }
        asm volatile("cp.async.commit_group;" ::: "memory");
    };

    const int NC = K / 16;
    load_chunk(0, 0);

    for (int i = 0; i < NC; i++) {
        int b = i & 1;
        if (i + 1 < NC) {
            load_chunk((i + 1) * 16, b ^ 1);
            asm volatile("cp.async.wait_group 1;" ::: "memory");
        } else {
            asm volatile("cp.async.wait_group 0;" ::: "memory");
        }
        __syncthreads();

        #pragma unroll
        for (int kk = 0; kk < 16; kk += 8) {
            uint32_t af[4][4], bf[4][2];
            #pragma unroll
            for (int mt = 0; mt < 4; mt++) {
                int m = wm + mt * 16 + row;
                af[mt][0] = __float_as_uint(As[b][m    ][kk + col    ]);
                af[mt][1] = __float_as_uint(As[b][m + 8][kk + col    ]);
                af[mt][2] = __float_as_uint(As[b][m    ][kk + col + 4]);
                af[mt][3] = __float_as_uint(As[b][m + 8][kk + col + 4]);
            }
            #pragma unroll
            for (int nt = 0; nt < 4; nt++) {
                int n = wn + nt * 8 + row;
                bf[nt][0] = __float_as_uint(Bs[b][kk + col    ][n]);
                bf[nt][1] = __float_as_uint(Bs[b][kk + col + 4][n]);
            }
            #pragma unroll
            for (int mt = 0; mt < 4; mt++)
                #pragma unroll
                for (int nt = 0; nt < 4; nt++)
                    mma_tf32(acc[mt][nt], af[mt], bf[nt]);
        }
        __syncthreads();
    }

    // -------- epilogue --------
    #pragma unroll
    for (int mt = 0; mt < 4; mt++) {
        #pragma unroll
        for (int nt = 0; nt < 4; nt++) {
            int m = m0 + wm + mt * 16 + row;
            int n = n0 + wn + nt * 8 + 2 * col;
            float2 bv = *(const float2*)(bias + n);
            #pragma unroll
            for (int half = 0; half < 2; half++) {
                int mg = m + half * 8;
                float2 o;
                o.x = acc[mt][nt][half * 2 + 0] + bv.x;
                o.y = acc[mt][nt][half * 2 + 1] + bv.y;
                if (EPI == 1) {
                    o.x = tf32r(gelu_f(o.x)); o.y = tf32r(gelu_f(o.y));
                } else if (EPI == 2) {
                    float2 e = *(const float2*)(extra + (size_t)mg * lde + n);
                    o.x = tf32r(o.x * e.x); o.y = tf32r(o.y * e.y);
                } else if (EPI == 3) {
                    float2 e = *(const float2*)(extra + (size_t)mg * lde + n);
                    o.x += e.x; o.y += e.y;
                }
                *(float2*)(C + (size_t)mg * ldc + n) = o;
            }
        }
    }
}

// ------------- weight pack + tf32 round: out[k*N+n] = rnd(in[k*ldin+off+n]) -------------
__global__ void pack_rnd(const float* __restrict__ in, int ldin, int off,
                         int N, int total, float* __restrict__ outp)
{
    int idx = blockIdx.x * 256 + threadIdx.x;
    if (idx >= total) return;
    int k = idx / N, n = idx % N;
    outp[idx] = tf32r(in[(size_t)k * ldin + off + n]);
}

// ---------------- LayerNorm over C=128, one warp per token (tf32-rounded out) ----------------
__global__ void ln_kernel(const float* __restrict__ x,
                          const float* __restrict__ g,
                          const float* __restrict__ b,
                          float* __restrict__ y)
{
    int warp = (blockIdx.x * blockDim.x + threadIdx.x) >> 5;
    int lane = threadIdx.x & 31;
    if (warp >= MM) return;
    float4 v = ((const float4*)(x + (size_t)warp * CC))[lane];
    float s = v.x + v.y + v.z + v.w;
    #pragma unroll
    for (int o = 16; o; o >>= 1) s += __shfl_xor_sync(0xffffffffu, s, o);
    float mu = s * (1.0f / CC);
    float dx = v.x - mu, dy = v.y - mu, dz = v.z - mu, dw = v.w - mu;
    float s2 = dx*dx + dy*dy + dz*dz + dw*dw;
    #pragma unroll
    for (int o = 16; o; o >>= 1) s2 += __shfl_xor_sync(0xffffffffu, s2, o);
    float r = rsqrtf(s2 * (1.0f / CC) + 1e-5f);
    float4 gg = ((const float4*)g)[lane];
    float4 bb = ((const float4*)b)[lane];
    float4 o4;
    o4.x = tf32r(dx * r * gg.x + bb.x);
    o4.y = tf32r(dy * r * gg.y + bb.y);
    o4.z = tf32r(dz * r * gg.z + bb.z);
    o4.w = tf32r(dw * r * gg.w + bb.w);
    ((float4*)(y + (size_t)warp * CC))[lane] = o4;
}

// ---------------- gates GEMV (fp32) ----------------
__global__ void gates_kernel(const float* __restrict__ y,
                             const float* __restrict__ fw,
                             const float* __restrict__ fb,
                             float* __restrict__ gates)
{
    __shared__ float ws[128][5];
    __shared__ float fbs[4];
    int tid = threadIdx.x;
    if (tid < 128) {
        #pragma unroll
        for (int j = 0; j < 4; j++) ws[tid][j] = fw[tid * FWLD + 256 + j];
    }
    if (tid < 4) fbs[tid] = fb[256 + tid];
    __syncthreads();
    int tok = (blockIdx.x * 256 + tid) >> 5;
    int lane = tid & 31;
    if (tok >= MM) return;
    float4 v = ((const float4*)(y + (size_t)tok * CC))[lane];
    int k0 = lane * 4;
    float s[4];
    #pragma unroll
    for (int j = 0; j < 4; j++) {
        s[j] = v.x * ws[k0][j] + v.y * ws[k0+1][j] + v.z * ws[k0+2][j] + v.w * ws[k0+3][j];
        #pragma unroll
        for (int o = 16; o; o >>= 1) s[j] += __shfl_xor_sync(0xffffffffu, s[j], o);
    }
    if (lane == 0) {
        #pragma unroll
        for (int j = 0; j < 4; j++) gates[(size_t)tok * 4 + j] = s[j] + fbs[j];
    }
}

// ---------------- depthwise conv KSxKS + gelu + gated accumulation ----------------
template<int KS, bool INIT>
__global__ void dwconv_kernel(const float* __restrict__ in,
                              const float* __restrict__ kern,
                              const float* __restrict__ gates,
                              float* __restrict__ out,
                              float* __restrict__ ctxall,
                              int gidx)
{
    constexpr int P = KS / 2, TW = 8, IW = TW + KS - 1;
    int c = threadIdx.x;
    int blk = blockIdx.x;
    int wt = blk % (WW / TW);
    int rem = blk / (WW / TW);
    int h = rem % HH;
    int b = rem / HH;
    int w0 = wt * TW;

    float kw[KS * KS];
    #pragma unroll
    for (int i = 0; i < KS * KS; i++) kw[i] = kern[i * CC + c];

    float acc[TW];
    #pragma unroll
    for (int o = 0; o < TW; o++) acc[o] = 0.0f;

    const float* base = in + (size_t)b * LL * CC + c;
    #pragma unroll
    for (int kh = 0; kh < KS; kh++) {
        int ih = h + kh - P;
        if (ih < 0 || ih >= HH) continue;
        float inv[IW];
        #pragma unroll
        for (int i = 0; i < IW; i++) {
            int iw = w0 - P + i;
            inv[i] = (iw >= 0 && iw < WW) ? base[((size_t)ih * WW + iw) * CC] : 0.0f;
        }
        #pragma unroll
        for (int kx = 0; kx < KS; kx++) {
            float wv = kw[kh * KS + kx];
            #pragma unroll
            for (int o = 0; o < TW; o++) acc[o] += inv[o + kx] * wv;
        }
    }
    size_t opix = (size_t)b * LL + (size_t)h * WW + w0;
    #pragma unroll
    for (int o = 0; o < TW; o++) {
        float v = gelu_f(acc[o]);
        out[(opix + o) * CC + c] = v;
        float gt = gates[(opix + o) * 4 + gidx];
        if (INIT) ctxall[(opix + o) * CC + c] = v * gt;
        else      ctxall[(opix + o) * CC + c] += v * gt;
    }
}

// ---------------- global mean pool over H*W per (b,c), + gelu ----------------
__global__ void pool_kernel(const float* __restrict__ ctx, float* __restrict__ pool)
{
    __shared__ float sm[8][128];
    int b = blockIdx.x;
    int tid = threadIdx.x;
    int c = tid & 127, s = tid >> 7;
    const float* p = ctx + ((size_t)b * LL + (size_t)s * (LL / 8)) * CC + c;
    float acc = 0.0f;
    for (int i = 0; i < LL / 8; i++) acc += p[(size_t)i * CC];
    sm[s][c] = acc;
    __syncthreads();
    if (s == 0) {
        float t = 0.0f;
        #pragma unroll
        for (int k = 0; k < 8; k++) t += sm[k][c];
        pool[b * CC + c] = gelu_f(t * (1.0f / LL));
    }
}

// ---------------- ctxall += pool[b,c] * gates[pix,3], tf32-rounded ----------------
__global__ void bcast_add_kernel(float* __restrict__ ctxall,
                                 const float* __restrict__ pool,
                                 const float* __restrict__ gates)
{
    int i = blockIdx.x * blockDim.x + threadIdx.x;
    if (i >= MM * (CC / 4)) return;
    int pix = i >> 5;
    int c4 = i & 31;
    int b = pix / LL;
    float gt = gates[(size_t)pix * 4 + 3];
    float4 p = ((const float4*)(pool + b * CC))[c4];
    float4* dst = (float4*)ctxall + i;
    float4 v = *dst;
    v.x = tf32r(v.x + p.x * gt); v.y = tf32r(v.y + p.y * gt);
    v.z = tf32r(v.z + p.z * gt); v.w = tf32r(v.w + p.w * gt);
    *dst = v;
}

// ---------------- launch ----------------
extern "C" void kernel_launch(void* const* d_in, const int* in_sizes, int n_in,
                              void* d_out, int out_size)
{
    const float* x      = (const float*)d_in[0];
    const float* f_w    = (const float*)d_in[1];
    const float* f_b    = (const float*)d_in[2];
    const float* k0     = (const float*)d_in[3];
    const float* k1     = (const float*)d_in[4];
    const float* k2     = (const float*)d_in[5];
    const float* h_w    = (const float*)d_in[6];
    const float* h_b    = (const float*)d_in[7];
    const float* proj_w = (const float*)d_in[8];
    const float* proj_b = (const float*)d_in[9];
    const float* ln1_g  = (const float*)d_in[10];
    const float* ln1_b  = (const float*)d_in[11];
    const float* ln2_g  = (const float*)d_in[12];
    const float* ln2_b  = (const float*)d_in[13];
    const float* fc1_w  = (const float*)d_in[14];
    const float* fc1_b  = (const float*)d_in[15];
    const float* fc2_w  = (const float*)d_in[16];
    const float* fc2_b  = (const float*)d_in[17];
    float* out = (float*)d_out;

    float *y, *q, *c0, *c1, *call, *gts, *pl, *x1, *hid, *wt;
    cudaGetSymbolAddress((void**)&y,    g_y);
    cudaGetSymbolAddress((void**)&q,    g_q);
    cudaGetSymbolAddress((void**)&c0,   g_ctx0);
    cudaGetSymbolAddress((void**)&c1,   g_ctx1);
    cudaGetSymbolAddress((void**)&call, g_ctxall);
    cudaGetSymbolAddress((void**)&gts,  g_gates);
    cudaGetSymbolAddress((void**)&pl,   g_pool);
    cudaGetSymbolAddress((void**)&x1,   g_x1);
    cudaGetSymbolAddress((void**)&hid,  g_hidden);
    cudaGetSymbolAddress((void**)&wt,   g_wt);

    const int MBLK = MM / 128;                 // 1568
    dim3 g1(MBLK, 1), g4(MBLK, 4);
    const int conv_grid = BB * HH * (WW / 8);  // 25088

    // 0. pack + tf32-round weights into contiguous [K,N]
    pack_rnd<<<64, 256>>>(f_w,    FWLD, 0,   128, 16384, wt + WT_FWQ);
    pack_rnd<<<64, 256>>>(f_w,    FWLD, 128, 128, 16384, wt + WT_FWC);
    pack_rnd<<<64, 256>>>(h_w,    128,  0,   128, 16384, wt + WT_H);
    pack_rnd<<<64, 256>>>(proj_w, 128,  0,   128, 16384, wt + WT_PROJ);
    pack_rnd<<<256, 256>>>(fc1_w, 512,  0,   512, 65536, wt + WT_FC1);
    pack_rnd<<<256, 256>>>(fc2_w, 128,  0,   128, 65536, wt + WT_FC2);

    // 1. y = LN1(x)   (tf32-rounded)
    ln_kernel<<<MM/8, 256>>>(x, ln1_g, ln1_b, y);
    // 2. q = y @ f_w[:, :128] + f_b[:128]
    mma_gemm<0><<<g1, 256>>>(y, CC, wt + WT_FWQ, 128, f_b,       q,  CC, nullptr, 0, CC);
    // 3. ctx = y @ f_w[:, 128:256] + f_b[128:256]
    mma_gemm<0><<<g1, 256>>>(y, CC, wt + WT_FWC, 128, f_b + 128, c0, CC, nullptr, 0, CC);
    // 4. gates = y @ f_w[:, 256:260] + f_b[256:260]
    gates_kernel<<<MM/8, 256>>>(y, f_w, f_b, gts);
    // 5-7. focal levels
    dwconv_kernel<3, true ><<<conv_grid, 128>>>(c0, k0, gts, c1, call, 0);
    dwconv_kernel<5, false><<<conv_grid, 128>>>(c1, k1, gts, c0, call, 1);
    dwconv_kernel<7, false><<<conv_grid, 128>>>(c0, k2, gts, c1, call, 2);
    // 8. pool = gelu(mean(ctx2))
    pool_kernel<<<BB, 1024>>>(c1, pl);
    // 9. ctxall += pool * gates[:,3]   (tf32-rounded)
    bcast_add_kernel<<<(MM * (CC/4) + 255) / 256, 256>>>(call, pl, gts);
    // 10. y = (ctxall @ h_w + h_b) * q   (rounded)
    mma_gemm<2><<<g1, 256>>>(call, CC, wt + WT_H, 128, h_b, y, CC, q, CC, CC);
    // 11. x1 = x + (y @ proj_w + proj_b)
    mma_gemm<3><<<g1, 256>>>(y, CC, wt + WT_PROJ, 128, proj_b, x1, CC, x, CC, CC);
    // 12. c0 = LN2(x1)  (rounded)
    ln_kernel<<<MM/8, 256>>>(x1, ln2_g, ln2_b, c0);
    // 13. hidden = gelu(c0 @ fc1_w + fc1_b)  (rounded)
    mma_gemm<1><<<g4, 256>>>(c0, CC, wt + WT_FC1, 512, fc1_b, hid, HID, nullptr, 0, CC);
    // 14. out = x1 + (hidden @ fc2_w + fc2_b)
    mma_gemm<3><<<g1, 256>>>(hid, HID, wt + WT_FC2, 128, fc2_b, out, CC, x1, CC, HID);
}

// round 5
// speedup vs baseline: 1.1529x; 1.1529x over previous
#include <cuda_runtime.h>
#include <cuda_bf16.h>
#include <math.h>
#include <stdint.h>

// Problem constants (B=64, H=W=56, C=128)
#define BB 64
#define HH 56
#define WW 56
#define CC 128
#define LL (HH*WW)            // 3136
#define MM (BB*LL)            // 200704
#define HID 512
#define FWLD 260              // 2C + FOCAL_LEVEL + 1

typedef __nv_bfloat16 bf16;
typedef __nv_bfloat162 bf162;

// ---------------- scratch (device globals; no allocs allowed) ----------------
__device__ bf16  g_y[(size_t)MM*CC];       // LN1 out (bf16)
__device__ bf16  g_q[(size_t)MM*CC];
__device__ bf16  g_c0[(size_t)MM*CC];      // ping (bf16)
__device__ bf16  g_c1[(size_t)MM*CC];      // pong
__device__ bf16  g_call[(size_t)MM*CC];    // ctx_all (bf16)
__device__ bf16  g_y2[(size_t)MM*CC];      // q * modulator
__device__ bf16  g_c2[(size_t)MM*CC];      // LN2 out
__device__ bf16  g_hid[(size_t)MM*HID];
__device__ float g_gates[(size_t)MM*4];
__device__ float g_pool[BB*CC];
__device__ float g_x1[(size_t)MM*CC];
__device__ bf16  g_wt[196608];             // packed bf16 weights, [N][K]

#define WT_FWQ  0        // [128,128]
#define WT_FWC  16384
#define WT_H    32768
#define WT_PROJ 49152
#define WT_FC1  65536    // [512,128]
#define WT_FC2  131072   // [128,512]

__device__ __forceinline__ float gelu_f(float x) {
    return 0.5f * x * (1.0f + erff(x * 0.7071067811865475f));
}
__device__ __forceinline__ uint32_t smem_u32(const void* p) {
    uint32_t a;
    asm("{ .reg .u64 t; cvta.to.shared.u64 t, %1; cvt.u32.u64 %0, t; }" : "=r"(a) : "l"(p));
    return a;
}
__device__ __forceinline__ void cp16(uint32_t dst, const void* src) {
    asm volatile("cp.async.cg.shared.global [%0], [%1], 16;" :: "r"(dst), "l"(src));
}
__device__ __forceinline__ void mma_bf16(float* d, const uint32_t* a, const uint32_t* b) {
    asm volatile(
        "mma.sync.aligned.m16n8k16.row.col.f32.bf16.bf16.f32 "
        "{%0,%1,%2,%3}, {%4,%5,%6,%7}, {%8,%9}, {%0,%1,%2,%3};"
        : "+f"(d[0]), "+f"(d[1]), "+f"(d[2]), "+f"(d[3])
        : "r"(a[0]), "r"(a[1]), "r"(a[2]), "r"(a[3]), "r"(b[0]), "r"(b[1]));
}

// ======== bf16 mma.sync GEMM: C[M,N] = epi(A[M,K] @ Bt[N,K]^T + bias) ========
// grid (M/128, N/128), 256 threads (8 warps 2x4), warp tile 64x32, BK=16.
// Smem rows: 12 uint32 words per 16-k chunk (8 data + 4 pad) -> conflict-free.
// EPI: 0 none->bf16, 1 gelu->bf16, 2 *extra(bf16)->bf16, 3 +extra(f32)->f32.
template<int EPI>
__global__ void __launch_bounds__(256, 2)
bf_gemm(const bf16* __restrict__ A, int lda,
        const bf16* __restrict__ Bt,
        const float* __restrict__ bias,
        void* __restrict__ Cp, int ldc,
        const void* __restrict__ extrap, int lde,
        int K)
{
    __shared__ uint32_t As2[2][128][12];
    __shared__ uint32_t Bs2[2][128][12];

    const int tid  = threadIdx.x;
    const int lane = tid & 31, warp = tid >> 5;
    const int row  = lane >> 2, col = lane & 3;
    const int wm   = (warp >> 2) * 64;
    const int wn   = (warp & 3) * 32;
    const int m0   = blockIdx.x * 128, n0 = blockIdx.y * 128;

    const uint32_t sA = smem_u32(As2), sB = smem_u32(Bs2);
    const bf16* Ab = A + (size_t)m0 * lda;
    const bf16* Bb = Bt + (size_t)n0 * K;

    float acc[4][4][4];
    #pragma unroll
    for (int i = 0; i < 4; i++)
        #pragma unroll
        for (int j = 0; j < 4; j++)
            #pragma unroll
            for (int r = 0; r < 4; r++) acc[i][j][r] = 0.0f;

    const int r_ld = tid >> 1, h_ld = tid & 1;   // 128 rows x 2 halves
    auto load_chunk = [&](int kc, int buf) {
        cp16(sA + (uint32_t)((((buf * 128 + r_ld) * 12) + h_ld * 4) * 4),
             Ab + (size_t)r_ld * lda + kc + h_ld * 8);
        cp16(sB + (uint32_t)((((buf * 128 + r_ld) * 12) + h_ld * 4) * 4),
             Bb + (size_t)r_ld * K + kc + h_ld * 8);
        asm volatile("cp.async.commit_group;" ::: "memory");
    };

    const int NC = K / 16;
    load_chunk(0, 0);

    for (int i = 0; i < NC; i++) {
        int b = i & 1;
        if (i + 1 < NC) {
            load_chunk((i + 1) * 16, b ^ 1);
            asm volatile("cp.async.wait_group 1;" ::: "memory");
        } else {
            asm volatile("cp.async.wait_group 0;" ::: "memory");
        }
        __syncthreads();

        uint32_t af[4][4], bfr[4][2];
        #pragma unroll
        for (int mt = 0; mt < 4; mt++) {
            int m = wm + mt * 16 + row;
            af[mt][0] = As2[b][m    ][col    ];
            af[mt][1] = As2[b][m + 8][col    ];
            af[mt][2] = As2[b][m    ][col + 4];
            af[mt][3] = As2[b][m + 8][col + 4];
        }
        #pragma unroll
        for (int nt = 0; nt < 4; nt++) {
            int n = wn + nt * 8 + row;
            bfr[nt][0] = Bs2[b][n][col    ];
            bfr[nt][1] = Bs2[b][n][col + 4];
        }
        #pragma unroll
        for (int mt = 0; mt < 4; mt++)
            #pragma unroll
            for (int nt = 0; nt < 4; nt++)
                mma_bf16(acc[mt][nt], af[mt], bfr[nt]);
        __syncthreads();
    }

    // -------- epilogue --------
    bf16*  Cb = (bf16*)Cp;
    float* Cf = (float*)Cp;
    const bf16*  Eb = (const bf16*)extrap;
    const float* Ef = (const float*)extrap;

    #pragma unroll
    for (int mt = 0; mt < 4; mt++) {
        #pragma unroll
        for (int nt = 0; nt < 4; nt++) {
            int m = m0 + wm + mt * 16 + row;
            int n = n0 + wn + nt * 8 + 2 * col;
            float2 bv = *(const float2*)(bias + n);
            #pragma unroll
            for (int half = 0; half < 2; half++) {
                int mg = m + half * 8;
                float2 o;
                o.x = acc[mt][nt][half * 2 + 0] + bv.x;
                o.y = acc[mt][nt][half * 2 + 1] + bv.y;
                if (EPI == 0) {
                    *(bf162*)(Cb + (size_t)mg * ldc + n) = __floats2bfloat162_rn(o.x, o.y);
                } else if (EPI == 1) {
                    o.x = gelu_f(o.x); o.y = gelu_f(o.y);
                    *(bf162*)(Cb + (size_t)mg * ldc + n) = __floats2bfloat162_rn(o.x, o.y);
                } else if (EPI == 2) {
                    float2 e = __bfloat1622float2(*(const bf162*)(Eb + (size_t)mg * lde + n));
                    o.x *= e.x; o.y *= e.y;
                    *(bf162*)(Cb + (size_t)mg * ldc + n) = __floats2bfloat162_rn(o.x, o.y);
                } else {
                    float2 e = *(const float2*)(Ef + (size_t)mg * lde + n);
                    o.x += e.x; o.y += e.y;
                    *(float2*)(Cf + (size_t)mg * ldc + n) = o;
                }
            }
        }
    }
}

// ------------- weight pack (transpose) to bf16: out[n*K+k] = in[k*ldin+off+n] -------------
__global__ void pack_wT(const float* __restrict__ in, int ldin, int off,
                        int K, int total, bf16* __restrict__ outp)
{
    int idx = blockIdx.x * 256 + threadIdx.x;
    if (idx >= total) return;
    int n = idx / K, k = idx % K;
    outp[idx] = __float2bfloat16(in[(size_t)k * ldin + off + n]);
}

// ---------------- LayerNorm over C=128, one warp per token, bf16 out ----------------
__global__ void ln_kernel(const float* __restrict__ x,
                          const float* __restrict__ g,
                          const float* __restrict__ b,
                          bf16* __restrict__ y)
{
    int warp = (blockIdx.x * blockDim.x + threadIdx.x) >> 5;
    int lane = threadIdx.x & 31;
    if (warp >= MM) return;
    float4 v = ((const float4*)(x + (size_t)warp * CC))[lane];
    float s = v.x + v.y + v.z + v.w;
    #pragma unroll
    for (int o = 16; o; o >>= 1) s += __shfl_xor_sync(0xffffffffu, s, o);
    float mu = s * (1.0f / CC);
    float dx = v.x - mu, dy = v.y - mu, dz = v.z - mu, dw = v.w - mu;
    float s2 = dx*dx + dy*dy + dz*dz + dw*dw;
    #pragma unroll
    for (int o = 16; o; o >>= 1) s2 += __shfl_xor_sync(0xffffffffu, s2, o);
    float r = rsqrtf(s2 * (1.0f / CC) + 1e-5f);
    float4 gg = ((const float4*)g)[lane];
    float4 bb = ((const float4*)b)[lane];
    bf162 p0 = __floats2bfloat162_rn(dx * r * gg.x + bb.x, dy * r * gg.y + bb.y);
    bf162 p1 = __floats2bfloat162_rn(dz * r * gg.z + bb.z, dw * r * gg.w + bb.w);
    uint2 u;
    u.x = *(uint32_t*)&p0; u.y = *(uint32_t*)&p1;
    ((uint2*)(y + (size_t)warp * CC))[lane] = u;
}

// ---------------- gates GEMV: gates[m,j] = y[m,:] @ f_w[:,256+j] + f_b[256+j] ----------------
__global__ void gates_kernel(const bf16* __restrict__ y,
                             const float* __restrict__ fw,
                             const float* __restrict__ fb,
                             float* __restrict__ gates)
{
    __shared__ float ws[128][5];
    __shared__ float fbs[4];
    int tid = threadIdx.x;
    if (tid < 128) {
        #pragma unroll
        for (int j = 0; j < 4; j++) ws[tid][j] = fw[tid * FWLD + 256 + j];
    }
    if (tid < 4) fbs[tid] = fb[256 + tid];
    __syncthreads();
    int tok = (blockIdx.x * 256 + tid) >> 5;
    int lane = tid & 31;
    if (tok >= MM) return;
    uint2 u = ((const uint2*)(y + (size_t)tok * CC))[lane];
    float2 v01 = __bfloat1622float2(*(bf162*)&u.x);
    float2 v23 = __bfloat1622float2(*(bf162*)&u.y);
    int k0 = lane * 4;
    float s[4];
    #pragma unroll
    for (int j = 0; j < 4; j++) {
        s[j] = v01.x * ws[k0][j] + v01.y * ws[k0+1][j] + v23.x * ws[k0+2][j] + v23.y * ws[k0+3][j];
        #pragma unroll
        for (int o = 16; o; o >>= 1) s[j] += __shfl_xor_sync(0xffffffffu, s[j], o);
    }
    if (lane == 0) {
        #pragma unroll
        for (int j = 0; j < 4; j++) gates[(size_t)tok * 4 + j] = s[j] + fbs[j];
    }
}

// ---------------- depthwise conv KSxKS + gelu + gated accumulation (bf16 I/O) ----------------
template<int KS, bool INIT>
__global__ void dwconv_kernel(const bf16* __restrict__ in,
                              const float* __restrict__ kern,
                              const float* __restrict__ gates,
                              bf16* __restrict__ out,
                              bf16* __restrict__ ctxall,
                              int gidx)
{
    constexpr int P = KS / 2, TW = 8, IW = TW + KS - 1;
    int c = threadIdx.x;
    int blk = blockIdx.x;
    int wt = blk % (WW / TW);
    int rem = blk / (WW / TW);
    int h = rem % HH;
    int b = rem / HH;
    int w0 = wt * TW;

    float kw[KS * KS];
    #pragma unroll
    for (int i = 0; i < KS * KS; i++) kw[i] = kern[i * CC + c];

    float acc[TW];
    #pragma unroll
    for (int o = 0; o < TW; o++) acc[o] = 0.0f;

    const bf16* base = in + (size_t)b * LL * CC + c;
    #pragma unroll
    for (int kh = 0; kh < KS; kh++) {
        int ih = h + kh - P;
        if (ih < 0 || ih >= HH) continue;
        float inv[IW];
        #pragma unroll
        for (int i = 0; i < IW; i++) {
            int iw = w0 - P + i;
            inv[i] = (iw >= 0 && iw < WW) ? __bfloat162float(base[((size_t)ih * WW + iw) * CC]) : 0.0f;
        }
        #pragma unroll
        for (int kx = 0; kx < KS; kx++) {
            float wv = kw[kh * KS + kx];
            #pragma unroll
            for (int o = 0; o < TW; o++) acc[o] += inv[o + kx] * wv;
        }
    }
    size_t opix = (size_t)b * LL + (size_t)h * WW + w0;
    #pragma unroll
    for (int o = 0; o < TW; o++) {
        float v = gelu_f(acc[o]);
        out[(opix + o) * CC + c] = __float2bfloat16(v);
        float gt = gates[(opix + o) * 4 + gidx];
        if (INIT) {
            ctxall[(opix + o) * CC + c] = __float2bfloat16(v * gt);
        } else {
            float cur = __bfloat162float(ctxall[(opix + o) * CC + c]);
            ctxall[(opix + o) * CC + c] = __float2bfloat16(cur + v * gt);
        }
    }
}

// ---------------- global mean pool over H*W per (b,c), + gelu ----------------
__global__ void pool_kernel(const bf16* __restrict__ ctx, float* __restrict__ pool)
{
    __shared__ float sm[8][128];
    int b = blockIdx.x;
    int tid = threadIdx.x;
    int c = tid & 127, s = tid >> 7;
    const bf16* p = ctx + ((size_t)b * LL + (size_t)s * (LL / 8)) * CC + c;
    float acc = 0.0f;
    for (int i = 0; i < LL / 8; i++) acc += __bfloat162float(p[(size_t)i * CC]);
    sm[s][c] = acc;
    __syncthreads();
    if (s == 0) {
        float t = 0.0f;
        #pragma unroll
        for (int k = 0; k < 8; k++) t += sm[k][c];
        pool[b * CC + c] = gelu_f(t * (1.0f / LL));
    }
}

// ---------------- ctxall += pool[b,c] * gates[pix,3] (bf16 RMW) ----------------
__global__ void bcast_add_kernel(bf16* __restrict__ ctxall,
                                 const float* __restrict__ pool,
                                 const float* __restrict__ gates)
{
    int i = blockIdx.x * blockDim.x + threadIdx.x;   // bf162 index over MM*CC/2
    if (i >= MM * (CC / 2)) return;
    int pix = i >> 6;                                // 64 bf162 per pixel
    int c2 = i & 63;
    int b = pix / LL;
    float gt = gates[(size_t)pix * 4 + 3];
    float2 pp = *(const float2*)(pool + b * CC + c2 * 2);
    bf162* dst = (bf162*)ctxall + i;
    float2 v = __bfloat1622float2(*dst);
    v.x += pp.x * gt; v.y += pp.y * gt;
    *dst = __floats2bfloat162_rn(v.x, v.y);
}

// ---------------- launch ----------------
extern "C" void kernel_launch(void* const* d_in, const int* in_sizes, int n_in,
                              void* d_out, int out_size)
{
    const float* x      = (const float*)d_in[0];
    const float* f_w    = (const float*)d_in[1];
    const float* f_b    = (const float*)d_in[2];
    const float* k0     = (const float*)d_in[3];
    const float* k1     = (const float*)d_in[4];
    const float* k2     = (const float*)d_in[5];
    const float* h_w    = (const float*)d_in[6];
    const float* h_b    = (const float*)d_in[7];
    const float* proj_w = (const float*)d_in[8];
    const float* proj_b = (const float*)d_in[9];
    const float* ln1_g  = (const float*)d_in[10];
    const float* ln1_b  = (const float*)d_in[11];
    const float* ln2_g  = (const float*)d_in[12];
    const float* ln2_b  = (const float*)d_in[13];
    const float* fc1_w  = (const float*)d_in[14];
    const float* fc1_b  = (const float*)d_in[15];
    const float* fc2_w  = (const float*)d_in[16];
    const float* fc2_b  = (const float*)d_in[17];
    float* out = (float*)d_out;

    bf16 *y, *q, *c0, *c1, *call, *y2, *c2, *hid, *wt;
    float *gts, *pl, *x1;
    cudaGetSymbolAddress((void**)&y,    g_y);
    cudaGetSymbolAddress((void**)&q,    g_q);
    cudaGetSymbolAddress((void**)&c0,   g_c0);
    cudaGetSymbolAddress((void**)&c1,   g_c1);
    cudaGetSymbolAddress((void**)&call, g_call);
    cudaGetSymbolAddress((void**)&y2,   g_y2);
    cudaGetSymbolAddress((void**)&c2,   g_c2);
    cudaGetSymbolAddress((void**)&hid,  g_hid);
    cudaGetSymbolAddress((void**)&gts,  g_gates);
    cudaGetSymbolAddress((void**)&pl,   g_pool);
    cudaGetSymbolAddress((void**)&x1,   g_x1);
    cudaGetSymbolAddress((void**)&wt,   g_wt);

    const int MBLK = MM / 128;                 // 1568
    dim3 g1(MBLK, 1), g4(MBLK, 4);
    const int conv_grid = BB * HH * (WW / 8);  // 25088

    // 0. pack + transpose weights to bf16 [N][K]
    pack_wT<<<64, 256>>>(f_w,    FWLD, 0,   128, 16384, wt + WT_FWQ);
    pack_wT<<<64, 256>>>(f_w,    FWLD, 128, 128, 16384, wt + WT_FWC);
    pack_wT<<<64, 256>>>(h_w,    128,  0,   128, 16384, wt + WT_H);
    pack_wT<<<64, 256>>>(proj_w, 128,  0,   128, 16384, wt + WT_PROJ);
    pack_wT<<<256, 256>>>(fc1_w, 512,  0,   128, 65536, wt + WT_FC1);   // [512,128]
    pack_wT<<<256, 256>>>(fc2_w, 128,  0,   512, 65536, wt + WT_FC2);   // [128,512]

    // 1. y = LN1(x)  (bf16)
    ln_kernel<<<MM/8, 256>>>(x, ln1_g, ln1_b, y);
    // 2. q = y @ f_w[:, :128] + f_b[:128]
    bf_gemm<0><<<g1, 256>>>(y, CC, wt + WT_FWQ, f_b,       q,  CC, nullptr, 0, CC);
    // 3. ctx = y @ f_w[:, 128:256] + f_b[128:256]
    bf_gemm<0><<<g1, 256>>>(y, CC, wt + WT_FWC, f_b + 128, c0, CC, nullptr, 0, CC);
    // 4. gates
    gates_kernel<<<MM/8, 256>>>(y, f_w, f_b, gts);
    // 5-7. focal levels
    dwconv_kernel<3, true ><<<conv_grid, 128>>>(c0, k0, gts, c1, call, 0);
    dwconv_kernel<5, false><<<conv_grid, 128>>>(c1, k1, gts, c0, call, 1);
    dwconv_kernel<7, false><<<conv_grid, 128>>>(c0, k2, gts, c1, call, 2);
    // 8. pool = gelu(mean(ctx3))
    pool_kernel<<<BB, 1024>>>(c1, pl);
    // 9. ctxall += pool * gates[:,3]
    bcast_add_kernel<<<(MM * (CC/2) + 255) / 256, 256>>>(call, pl, gts);
    // 10. y2 = (ctxall @ h_w + h_b) * q
    bf_gemm<2><<<g1, 256>>>(call, CC, wt + WT_H, h_b, y2, CC, q, CC, CC);
    // 11. x1 = x + (y2 @ proj_w + proj_b)   (fp32 out)
    bf_gemm<3><<<g1, 256>>>(y2, CC, wt + WT_PROJ, proj_b, x1, CC, x, CC, CC);
    // 12. c2 = LN2(x1)  (bf16)
    ln_kernel<<<MM/8, 256>>>(x1, ln2_g, ln2_b, c2);
    // 13. hid = gelu(c2 @ fc1_w + fc1_b)  (bf16)
    bf_gemm<1><<<g4, 256>>>(c2, CC, wt + WT_FC1, fc1_b, hid, HID, nullptr, 0, CC);
    // 14. out = x1 + (hid @ fc2_w + fc2_b)  (fp32 out)
    bf_gemm<3><<<g1, 256>>>(hid, HID, wt + WT_FC2, fc2_b, out, CC, x1, CC, HID);
}

// round 6
// speedup vs baseline: 1.4574x; 1.2641x over previous
#include <cuda_runtime.h>
#include <cuda_bf16.h>
#include <math.h>
#include <stdint.h>

// Problem constants (B=64, H=W=56, C=128)
#define BB 64
#define HH 56
#define WW 56
#define CC 128
#define LL (HH*WW)            // 3136
#define MM (BB*LL)            // 200704
#define HID 512
#define FWLD 260

typedef __nv_bfloat16 bf16;
typedef __nv_bfloat162 bf162;

// ---------------- scratch ----------------
__device__ bf16  g_y[(size_t)MM*CC];
__device__ bf16  g_q[(size_t)MM*CC];
__device__ bf16  g_c0[(size_t)MM*CC];
__device__ bf16  g_c1[(size_t)MM*CC];
__device__ bf16  g_call[(size_t)MM*CC];
__device__ bf16  g_y2[(size_t)MM*CC];
__device__ bf16  g_c2[(size_t)MM*CC];
__device__ bf16  g_hid[(size_t)MM*HID];
__device__ float g_gates[(size_t)MM*4];
__device__ float g_pool[BB*CC];
__device__ float g_x1[(size_t)MM*CC];
__device__ bf16  g_wt[196608];             // packed bf16 weights, [N][K]

#define WT_QC   0        // [256,128]  (q then ctx)
#define WT_H    32768    // [128,128]
#define WT_PROJ 49152    // [128,128]
#define WT_FC1  65536    // [512,128]
#define WT_FC2  131072   // [128,512]

__device__ __forceinline__ float gelu_f(float x) {
    float y = 0.7978845608028654f * (x + 0.044715f * x * x * x);
    float t; asm("tanh.approx.f32 %0, %1;" : "=f"(t) : "f"(y));
    return 0.5f * x * (1.0f + t);
}
__device__ __forceinline__ uint32_t smem_u32(const void* p) {
    uint32_t a;
    asm("{ .reg .u64 t; cvta.to.shared.u64 t, %1; cvt.u32.u64 %0, t; }" : "=r"(a) : "l"(p));
    return a;
}
__device__ __forceinline__ void cp16(uint32_t dst, const void* src) {
    asm volatile("cp.async.cg.shared.global [%0], [%1], 16;" :: "r"(dst), "l"(src));
}
__device__ __forceinline__ void mma_bf16(float* d, const uint32_t* a, const uint32_t* b) {
    asm volatile(
        "mma.sync.aligned.m16n8k16.row.col.f32.bf16.bf16.f32 "
        "{%0,%1,%2,%3}, {%4,%5,%6,%7}, {%8,%9}, {%0,%1,%2,%3};"
        : "+f"(d[0]), "+f"(d[1]), "+f"(d[2]), "+f"(d[3])
        : "r"(a[0]), "r"(a[1]), "r"(a[2]), "r"(a[3]), "r"(b[0]), "r"(b[1]));
}

// ======== bf16 mma.sync GEMM: C[M,N] = epi(A[M,K] @ Bt[N,K]^T + bias) ========
// grid (M/128, N/128), 256 threads (8 warps 2x4), warp tile 64x32, BK=32.
// EPI: 0 none->bf16, 1 gelu->bf16, 2 *extra(bf16)->bf16, 3 +extra(f32)->f32,
//      4 dual bf16 out (n0==0 -> Cp, else -> extrap).
template<int EPI>
__global__ void __launch_bounds__(256, 2)
bf_gemm(const bf16* __restrict__ A, int lda,
        const bf16* __restrict__ Bt,
        const float* __restrict__ bias,
        void* __restrict__ Cp, int ldc,
        const void* __restrict__ extrap, int lde,
        int K)
{
    __shared__ uint32_t As2[2][128][20];   // 32 halves = 16 words + 4 pad
    __shared__ uint32_t Bs2[2][128][20];

    const int tid  = threadIdx.x;
    const int lane = tid & 31, warp = tid >> 5;
    const int row  = lane >> 2, col = lane & 3;
    const int wm   = (warp >> 2) * 64;
    const int wn   = (warp & 3) * 32;
    const int m0   = blockIdx.x * 128, n0 = blockIdx.y * 128;

    const uint32_t sA = smem_u32(As2), sB = smem_u32(Bs2);
    const bf16* Ab = A + (size_t)m0 * lda;
    const bf16* Bb = Bt + (size_t)n0 * K;

    float acc[4][4][4];
    #pragma unroll
    for (int i = 0; i < 4; i++)
        #pragma unroll
        for (int j = 0; j < 4; j++)
            #pragma unroll
            for (int r = 0; r < 4; r++) acc[i][j][r] = 0.0f;

    const int r_ld = tid >> 2, s_ld = tid & 3;   // 128 rows x 4 x 16B
    auto load_chunk = [&](int kc, int buf) {
        #pragma unroll
        for (int t = 0; t < 2; t++) {
            int r = r_ld + t * 64;
            cp16(sA + (uint32_t)((((buf * 128 + r) * 20) + s_ld * 4) * 4),
                 Ab + (size_t)r * lda + kc + s_ld * 8);
        }
        #pragma unroll
        for (int t = 0; t < 2; t++) {
            int r = r_ld + t * 64;
            cp16(sB + (uint32_t)((((buf * 128 + r) * 20) + s_ld * 4) * 4),
                 Bb + (size_t)r * K + kc + s_ld * 8);
        }
        asm volatile("cp.async.commit_group;" ::: "memory");
    };

    const int NC = K / 32;
    load_chunk(0, 0);

    for (int i = 0; i < NC; i++) {
        int b = i & 1;
        if (i + 1 < NC) {
            load_chunk((i + 1) * 32, b ^ 1);
            asm volatile("cp.async.wait_group 1;" ::: "memory");
        } else {
            asm volatile("cp.async.wait_group 0;" ::: "memory");
        }
        __syncthreads();

        #pragma unroll
        for (int kk = 0; kk < 2; kk++) {           // two k16 sub-chunks
            const int wo = kk * 8;
            uint32_t af[4][4], bfr[4][2];
            #pragma unroll
            for (int mt = 0; mt < 4; mt++) {
                int m = wm + mt * 16 + row;
                af[mt][0] = As2[b][m    ][wo + col    ];
                af[mt][1] = As2[b][m + 8][wo + col    ];
                af[mt][2] = As2[b][m    ][wo + col + 4];
                af[mt][3] = As2[b][m + 8][wo + col + 4];
            }
            #pragma unroll
            for (int nt = 0; nt < 4; nt++) {
                int n = wn + nt * 8 + row;
                bfr[nt][0] = Bs2[b][n][wo + col    ];
                bfr[nt][1] = Bs2[b][n][wo + col + 4];
            }
            #pragma unroll
            for (int mt = 0; mt < 4; mt++)
                #pragma unroll
                for (int nt = 0; nt < 4; nt++)
                    mma_bf16(acc[mt][nt], af[mt], bfr[nt]);
        }
        __syncthreads();
    }

    // -------- epilogue --------
    bf16*  Cb = (bf16*)Cp;
    float* Cf = (float*)Cp;
    const bf16*  Eb = (const bf16*)extrap;
    const float* Ef = (const float*)extrap;

    #pragma unroll
    for (int mt = 0; mt < 4; mt++) {
        #pragma unroll
        for (int nt = 0; nt < 4; nt++) {
            int m = m0 + wm + mt * 16 + row;
            int n = n0 + wn + nt * 8 + 2 * col;
            float2 bv = *(const float2*)(bias + n);
            #pragma unroll
            for (int half = 0; half < 2; half++) {
                int mg = m + half * 8;
                float2 o;
                o.x = acc[mt][nt][half * 2 + 0] + bv.x;
                o.y = acc[mt][nt][half * 2 + 1] + bv.y;
                if (EPI == 0) {
                    *(bf162*)(Cb + (size_t)mg * ldc + n) = __floats2bfloat162_rn(o.x, o.y);
                } else if (EPI == 1) {
                    o.x = gelu_f(o.x); o.y = gelu_f(o.y);
                    *(bf162*)(Cb + (size_t)mg * ldc + n) = __floats2bfloat162_rn(o.x, o.y);
                } else if (EPI == 2) {
                    float2 e = __bfloat1622float2(*(const bf162*)(Eb + (size_t)mg * lde + n));
                    o.x *= e.x; o.y *= e.y;
                    *(bf162*)(Cb + (size_t)mg * ldc + n) = __floats2bfloat162_rn(o.x, o.y);
                } else if (EPI == 3) {
                    float2 e = *(const float2*)(Ef + (size_t)mg * lde + n);
                    o.x += e.x; o.y += e.y;
                    *(float2*)(Cf + (size_t)mg * ldc + n) = o;
                } else {  // EPI == 4: dual output (q / ctx)
                    bf16* dst = (n0 == 0) ? Cb : (bf16*)const_cast<void*>(extrap);
                    int nl = n - n0;
                    *(bf162*)(dst + (size_t)mg * ldc + nl) = __floats2bfloat162_rn(o.x, o.y);
                }
            }
        }
    }
}

// ------------- fused weight pack (transpose) to bf16 [N][K] -------------
__global__ void pack_all(const float* __restrict__ f_w, const float* __restrict__ h_w,
                         const float* __restrict__ proj_w, const float* __restrict__ fc1_w,
                         const float* __restrict__ fc2_w, bf16* __restrict__ wt)
{
    int idx = blockIdx.x * 256 + threadIdx.x;
    if (idx >= 196608) return;
    float v;
    if (idx < 32768) {                       // QC: n in [0,256), k in [0,128)
        int n = idx >> 7, k = idx & 127;
        v = f_w[k * FWLD + n];
    } else if (idx < 49152) {
        int j = idx - 32768; int n = j >> 7, k = j & 127;
        v = h_w[k * 128 + n];
    } else if (idx < 65536) {
        int j = idx - 49152; int n = j >> 7, k = j & 127;
        v = proj_w[k * 128 + n];
    } else if (idx < 131072) {
        int j = idx - 65536; int n = j >> 7, k = j & 127;
        v = fc1_w[k * 512 + n];
    } else {
        int j = idx - 131072; int n = j / 512, k = j % 512;
        v = fc2_w[k * 128 + n];
    }
    wt[idx] = __float2bfloat16(v);
}

// ---------------- LayerNorm over C=128, one warp per token, bf16 out ----------------
__global__ void ln_kernel(const float* __restrict__ x,
                          const float* __restrict__ g,
                          const float* __restrict__ b,
                          bf16* __restrict__ y)
{
    int warp = (blockIdx.x * blockDim.x + threadIdx.x) >> 5;
    int lane = threadIdx.x & 31;
    if (warp >= MM) return;
    float4 v = ((const float4*)(x + (size_t)warp * CC))[lane];
    float s = v.x + v.y + v.z + v.w;
    #pragma unroll
    for (int o = 16; o; o >>= 1) s += __shfl_xor_sync(0xffffffffu, s, o);
    float mu = s * (1.0f / CC);
    float dx = v.x - mu, dy = v.y - mu, dz = v.z - mu, dw = v.w - mu;
    float s2 = dx*dx + dy*dy + dz*dz + dw*dw;
    #pragma unroll
    for (int o = 16; o; o >>= 1) s2 += __shfl_xor_sync(0xffffffffu, s2, o);
    float r = rsqrtf(s2 * (1.0f / CC) + 1e-5f);
    float4 gg = ((const float4*)g)[lane];
    float4 bb = ((const float4*)b)[lane];
    bf162 p0 = __floats2bfloat162_rn(dx * r * gg.x + bb.x, dy * r * gg.y + bb.y);
    bf162 p1 = __floats2bfloat162_rn(dz * r * gg.z + bb.z, dw * r * gg.w + bb.w);
    uint2 u;
    u.x = *(uint32_t*)&p0; u.y = *(uint32_t*)&p1;
    ((uint2*)(y + (size_t)warp * CC))[lane] = u;
}

// ---------------- gates GEMV ----------------
__global__ void gates_kernel(const bf16* __restrict__ y,
                             const float* __restrict__ fw,
                             const float* __restrict__ fb,
                             float* __restrict__ gates)
{
    __shared__ float ws[128][5];
    __shared__ float fbs[4];
    int tid = threadIdx.x;
    if (tid < 128) {
        #pragma unroll
        for (int j = 0; j < 4; j++) ws[tid][j] = fw[tid * FWLD + 256 + j];
    }
    if (tid < 4) fbs[tid] = fb[256 + tid];
    __syncthreads();
    int tok = (blockIdx.x * 256 + tid) >> 5;
    int lane = tid & 31;
    if (tok >= MM) return;
    uint2 u = ((const uint2*)(y + (size_t)tok * CC))[lane];
    float2 v01 = __bfloat1622float2(*(bf162*)&u.x);
    float2 v23 = __bfloat1622float2(*(bf162*)&u.y);
    int k0 = lane * 4;
    float s[4];
    #pragma unroll
    for (int j = 0; j < 4; j++) {
        s[j] = v01.x * ws[k0][j] + v01.y * ws[k0+1][j] + v23.x * ws[k0+2][j] + v23.y * ws[k0+3][j];
        #pragma unroll
        for (int o = 16; o; o >>= 1) s[j] += __shfl_xor_sync(0xffffffffu, s[j], o);
    }
    if (lane == 0) {
        #pragma unroll
        for (int j = 0; j < 4; j++) gates[(size_t)tok * 4 + j] = s[j] + fbs[j];
    }
}

// ---------------- depthwise conv (channel-pair vectorized) ----------------
// block: 64 threads = 64 channel pairs; each thread computes 8 pixels x 2 ch.
template<int KS, bool INIT>
__global__ void dwconv_kernel(const bf16* __restrict__ in,
                              const float* __restrict__ kern,
                              const float* __restrict__ gates,
                              bf16* __restrict__ out,
                              bf16* __restrict__ ctxall,
                              int gidx)
{
    constexpr int P = KS / 2, TW = 8, IW = TW + KS - 1;
    int cp = threadIdx.x;                     // channel pair 0..63
    int blk = blockIdx.x;
    int wt = blk % (WW / TW);
    int rem = blk / (WW / TW);
    int h = rem % HH;
    int b = rem / HH;
    int w0 = wt * TW;

    float2 kw[KS * KS];
    #pragma unroll
    for (int i = 0; i < KS * KS; i++)
        kw[i] = make_float2(kern[i * CC + 2 * cp], kern[i * CC + 2 * cp + 1]);

    float2 acc[TW];
    #pragma unroll
    for (int o = 0; o < TW; o++) acc[o] = make_float2(0.0f, 0.0f);

    const bf162* base = (const bf162*)in + (size_t)b * LL * 64 + cp;
    #pragma unroll
    for (int kh = 0; kh < KS; kh++) {
        int ih = h + kh - P;
        if (ih < 0 || ih >= HH) continue;
        float2 inv[IW];
        #pragma unroll
        for (int i = 0; i < IW; i++) {
            int iw = w0 - P + i;
            inv[i] = (iw >= 0 && iw < WW)
                   ? __bfloat1622float2(base[((size_t)ih * WW + iw) * 64])
                   : make_float2(0.0f, 0.0f);
        }
        #pragma unroll
        for (int kx = 0; kx < KS; kx++) {
            float2 wv = kw[kh * KS + kx];
            #pragma unroll
            for (int o = 0; o < TW; o++) {
                acc[o].x += inv[o + kx].x * wv.x;
                acc[o].y += inv[o + kx].y * wv.y;
            }
        }
    }
    size_t opix = (size_t)b * LL + (size_t)h * WW + w0;
    bf162* outp = (bf162*)out;
    bf162* cap  = (bf162*)ctxall;
    #pragma unroll
    for (int o = 0; o < TW; o++) {
        float vx = gelu_f(acc[o].x), vy = gelu_f(acc[o].y);
        outp[(opix + o) * 64 + cp] = __floats2bfloat162_rn(vx, vy);
        float gt = gates[(opix + o) * 4 + gidx];
        if (INIT) {
            cap[(opix + o) * 64 + cp] = __floats2bfloat162_rn(vx * gt, vy * gt);
        } else {
            float2 cur = __bfloat1622float2(cap[(opix + o) * 64 + cp]);
            cap[(opix + o) * 64 + cp] = __floats2bfloat162_rn(cur.x + vx * gt, cur.y + vy * gt);
        }
    }
}

// ---------------- global mean pool + gelu ----------------
__global__ void pool_kernel(const bf16* __restrict__ ctx, float* __restrict__ pool)
{
    __shared__ float sm[8][128];
    int b = blockIdx.x;
    int tid = threadIdx.x;
    int c = tid & 127, s = tid >> 7;
    const bf16* p = ctx + ((size_t)b * LL + (size_t)s * (LL / 8)) * CC + c;
    float acc = 0.0f;
    for (int i = 0; i < LL / 8; i++) acc += __bfloat162float(p[(size_t)i * CC]);
    sm[s][c] = acc;
    __syncthreads();
    if (s == 0) {
        float t = 0.0f;
        #pragma unroll
        for (int k = 0; k < 8; k++) t += sm[k][c];
        pool[b * CC + c] = gelu_f(t * (1.0f / LL));
    }
}

// ---------------- ctxall += pool[b,c] * gates[pix,3] ----------------
__global__ void bcast_add_kernel(bf16* __restrict__ ctxall,
                                 const float* __restrict__ pool,
                                 const float* __restrict__ gates)
{
    int i = blockIdx.x * blockDim.x + threadIdx.x;
    if (i >= MM * (CC / 2)) return;
    int pix = i >> 6;
    int c2 = i & 63;
    int b = pix / LL;
    float gt = gates[(size_t)pix * 4 + 3];
    float2 pp = *(const float2*)(pool + b * CC + c2 * 2);
    bf162* dst = (bf162*)ctxall + i;
    float2 v = __bfloat1622float2(*dst);
    v.x += pp.x * gt; v.y += pp.y * gt;
    *dst = __floats2bfloat162_rn(v.x, v.y);
}

// ---------------- launch ----------------
extern "C" void kernel_launch(void* const* d_in, const int* in_sizes, int n_in,
                              void* d_out, int out_size)
{
    const float* x      = (const float*)d_in[0];
    const float* f_w    = (const float*)d_in[1];
    const float* f_b    = (const float*)d_in[2];
    const float* k0     = (const float*)d_in[3];
    const float* k1     = (const float*)d_in[4];
    const float* k2     = (const float*)d_in[5];
    const float* h_w    = (const float*)d_in[6];
    const float* h_b    = (const float*)d_in[7];
    const float* proj_w = (const float*)d_in[8];
    const float* proj_b = (const float*)d_in[9];
    const float* ln1_g  = (const float*)d_in[10];
    const float* ln1_b  = (const float*)d_in[11];
    const float* ln2_g  = (const float*)d_in[12];
    const float* ln2_b  = (const float*)d_in[13];
    const float* fc1_w  = (const float*)d_in[14];
    const float* fc1_b  = (const float*)d_in[15];
    const float* fc2_w  = (const float*)d_in[16];
    const float* fc2_b  = (const float*)d_in[17];
    float* out = (float*)d_out;

    bf16 *y, *q, *c0, *c1, *call, *y2, *c2, *hid, *wt;
    float *gts, *pl, *x1;
    cudaGetSymbolAddress((void**)&y,    g_y);
    cudaGetSymbolAddress((void**)&q,    g_q);
    cudaGetSymbolAddress((void**)&c0,   g_c0);
    cudaGetSymbolAddress((void**)&c1,   g_c1);
    cudaGetSymbolAddress((void**)&call, g_call);
    cudaGetSymbolAddress((void**)&y2,   g_y2);
    cudaGetSymbolAddress((void**)&c2,   g_c2);
    cudaGetSymbolAddress((void**)&hid,  g_hid);
    cudaGetSymbolAddress((void**)&gts,  g_gates);
    cudaGetSymbolAddress((void**)&pl,   g_pool);
    cudaGetSymbolAddress((void**)&x1,   g_x1);
    cudaGetSymbolAddress((void**)&wt,   g_wt);

    const int MBLK = MM / 128;                 // 1568
    dim3 g1(MBLK, 1), g2(MBLK, 2), g4(MBLK, 4);
    const int conv_grid = BB * HH * (WW / 8);  // 25088

    // 1. pack weights (single kernel)
    pack_all<<<768, 256>>>(f_w, h_w, proj_w, fc1_w, fc2_w, wt);
    // 2. y = LN1(x)
    ln_kernel<<<MM/8, 256>>>(x, ln1_g, ln1_b, y);
    // 3. fused q|ctx GEMM (N=256)
    bf_gemm<4><<<g2, 256>>>(y, CC, wt + WT_QC, f_b, q, CC, c0, CC, CC);
    // 4. gates
    gates_kernel<<<MM/8, 256>>>(y, f_w, f_b, gts);
    // 5-7. focal levels
    dwconv_kernel<3, true ><<<conv_grid, 64>>>(c0, k0, gts, c1, call, 0);
    dwconv_kernel<5, false><<<conv_grid, 64>>>(c1, k1, gts, c0, call, 1);
    dwconv_kernel<7, false><<<conv_grid, 64>>>(c0, k2, gts, c1, call, 2);
    // 8. pool
    pool_kernel<<<BB, 1024>>>(c1, pl);
    // 9. ctxall += pool * gates[:,3]
    bcast_add_kernel<<<(MM * (CC/2) + 255) / 256, 256>>>(call, pl, gts);
    // 10. y2 = (ctxall @ h_w + h_b) * q
    bf_gemm<2><<<g1, 256>>>(call, CC, wt + WT_H, h_b, y2, CC, q, CC, CC);
    // 11. x1 = x + (y2 @ proj_w + proj_b)   (fp32)
    bf_gemm<3><<<g1, 256>>>(y2, CC, wt + WT_PROJ, proj_b, x1, CC, x, CC, CC);
    // 12. c2 = LN2(x1)
    ln_kernel<<<MM/8, 256>>>(x1, ln2_g, ln2_b, c2);
    // 13. hid = gelu(c2 @ fc1_w + fc1_b)
    bf_gemm<1><<<g4, 256>>>(c2, CC, wt + WT_FC1, fc1_b, hid, HID, nullptr, 0, CC);
    // 14. out = x1 + (hid @ fc2_w + fc2_b)   (fp32)
    bf_gemm<3><<<g1, 256>>>(hid, HID, wt + WT_FC2, fc2_b, out, CC, x1, CC, HID);
}